// round 11
// baseline (speedup 1.0000x reference)
#include <cuda_runtime.h>
#include <cstdint>

#define N_DOM 6
#define B_    4
#define T_    1024
#define D_    768
#define P_    3
#define H_    2
#define DH    32
#define I_    64
#define S_    (P_*T_)          // 3072
#define NBT   (N_DOM*B_*T_)    // 24576
#define NBS   (N_DOM*B_*S_)    // 73728
#define SG_   (S_/8)           // 384 key-groups per (nb,h)

// Scratch (allocation-free rule: device globals)
__device__ float g_q[NBT*I_];
__device__ float g_k[NBS*I_];   // fragment-major: [nbh][sg][kd][lane]{x,y}
__device__ float g_v[NBS*I_];   // fragment-major: [nbh][sg][dt][lane]{x,y}
__device__ float g_o[NBT*I_];
__device__ float g_WkF[I_*D_];  // frag-major pair-packed: [c][nh][nt][ksp][lane][4]
__device__ float g_WvF[I_*D_];
__device__ float g_WqF[N_DOM*I_*D_];
__device__ float g_WoT[N_DOM*D_*I_];  // plain K-major transpose (R8)
__device__ float g_bias[B_*S_];  // (1-mask)*-10000*log2(e), pos8-permuted per 8-group

// ---------------------------------------------------------------------------
// helpers
// ---------------------------------------------------------------------------
__device__ __forceinline__ uint32_t smem_u32(const void* p) {
    uint32_t a;
    asm("{ .reg .u64 t; cvta.to.shared.u64 t, %1; cvt.u32.u64 %0, t; }" : "=r"(a) : "l"(p));
    return a;
}
__device__ __forceinline__ void cpa16(void* s, const void* g) {
    uint32_t sa = smem_u32(s);
    asm volatile("cp.async.cg.shared.global [%0], [%1], 16;" :: "r"(sa), "l"(g) : "memory");
}
#define CP_COMMIT() asm volatile("cp.async.commit_group;" ::: "memory")
#define CP_WAIT0()  asm volatile("cp.async.wait_group 0;" ::: "memory")
#define CP_WAIT1()  asm volatile("cp.async.wait_group 1;" ::: "memory")

__device__ __forceinline__ float to_tf32_rna(float x) {
    uint32_t u;
    asm("cvt.rna.tf32.f32 %0, %1;" : "=r"(u) : "f"(x));
    return __uint_as_float(u);
}
__device__ __forceinline__ uint32_t fbits(float x) { return __float_as_uint(x); }

__device__ __forceinline__ void mma8(float* c, const uint32_t* a, const uint32_t* b) {
    asm volatile(
        "mma.sync.aligned.m16n8k8.row.col.f32.tf32.tf32.f32 "
        "{%0,%1,%2,%3}, {%4,%5,%6,%7}, {%8,%9}, {%0,%1,%2,%3};"
        : "+f"(c[0]), "+f"(c[1]), "+f"(c[2]), "+f"(c[3])
        : "r"(a[0]), "r"(a[1]), "r"(a[2]), "r"(a[3]), "r"(b[0]), "r"(b[1]));
}

// permutation within 8-groups: logical r -> stored pos (pairs (r, r+4) adjacent)
__device__ __forceinline__ int pos8(int r) { return (r < 4) ? 2 * r : 2 * (r - 4) + 1; }

// ---------------------------------------------------------------------------
// Kernel 0: weight prep. Wk/Wv/Wq fragment-major pair-packed; Wo K-major
// transpose (R8); permuted bias table (log2 domain).
// ---------------------------------------------------------------------------
__global__ void __launch_bounds__(256) prep_weights(
    const float* __restrict__ Wk, const float* __restrict__ Wv,
    const float* __restrict__ Wq, const float* __restrict__ Wo,
    const int* __restrict__ mask)
{
    int idx = blockIdx.x * 256 + threadIdx.x;
    // Wk/Wv frag-major: [c][nh][nt][ksp][lane][q]
    if (idx < I_ * D_) {
        int q = idx & 3, lane = (idx >> 2) & 31, ksp = (idx >> 7) & 1;
        int nt = (idx >> 8) & 3, nh = (idx >> 10) & 1, c = idx >> 11;
        int lr = lane >> 2, lc = lane & 3;
        int ks = ksp * 2 + (q >> 1), comp = q & 1;
        int d = c * 32 + ks * 8 + lc + comp * 4;
        int i = nh * 32 + nt * 8 + lr;
        g_WkF[idx] = to_tf32_rna(Wk[d * I_ + i]);
        g_WvF[idx] = to_tf32_rna(Wv[d * I_ + i]);
    }
    // Wq frag-major per domain (same mapping)
    if (idx < N_DOM * I_ * D_) {
        int n = idx / (I_ * D_), r = idx % (I_ * D_);
        int q = r & 3, lane = (r >> 2) & 31, ksp = (r >> 7) & 1;
        int nt = (r >> 8) & 3, nh = (r >> 10) & 1, c = r >> 11;
        int lr = lane >> 2, lc = lane & 3;
        int ks = ksp * 2 + (q >> 1), comp = q & 1;
        int d = c * 32 + ks * 8 + lc + comp * 4;
        int i = nh * 32 + nt * 8 + lr;
        g_WqF[idx] = to_tf32_rna(Wq[((size_t)n * D_ + d) * I_ + i]);
    }
    // Wo: plain K-major transpose (R8 layout)
    if (idx < N_DOM * D_ * I_) {
        int n = idx / (D_ * I_), r = idx % (D_ * I_);
        int d = r / I_, i = r % I_;
        g_WoT[idx] = to_tf32_rna(Wo[((size_t)n * I_ + i) * D_ + d]);
    }
    if (idx < B_ * S_) {
        int b = idx / S_, s = idx % S_;
        float v = (1.0f - (float)mask[b * T_ + (s % T_)]) * -10000.0f
                  * 1.4426950408889634f;
        g_bias[b * S_ + (s & ~7) + pos8(s & 7)] = v;
    }
}

// ---------------------------------------------------------------------------
// Kernel 1: K+V projection. Pair-packed frag-major B; R8/R10 epilogue.
// ---------------------------------------------------------------------------
#define KV_A_OFF   0
#define KV_A_BUF   (128*36*4)              // 18432
#define KV_BK_OFF  (2*KV_A_BUF)            // 36864
#define KV_B_BUF   8192
#define KV_BV_OFF  (KV_BK_OFF + 2*KV_B_BUF)// 53248
#define KV_SMEM    (KV_BV_OFF + 2*KV_B_BUF)// 69632

__global__ void __launch_bounds__(256) proj_kv_mma(const float* __restrict__ hist)
{
    extern __shared__ char sm[];
    const int tid  = threadIdx.x;
    const int wid  = tid >> 5;
    const int lane = tid & 31;
    const int lr = lane >> 2, lc = lane & 3;
    const int m0 = (wid & 3) * 32;
    const int nh = wid >> 2;               // n0 = nh*32

    const int hr0 = blockIdx.x * 128;
    const float* Ab = hist + (size_t)hr0 * D_;

    auto stage = [&](int c, int buf) {
        float* A  = (float*)(sm + KV_A_OFF  + buf * KV_A_BUF);
        float* Bk = (float*)(sm + KV_BK_OFF + buf * KV_B_BUF);
        float* Bv = (float*)(sm + KV_BV_OFF + buf * KV_B_BUF);
        int kk = c * 32;
        #pragma unroll
        for (int q = 0; q < 4; q++) {
            int e = tid + q * 256;
            int r = e >> 3, c4 = (e & 7) * 4;
            cpa16(&A[r * 36 + c4], Ab + (size_t)r * D_ + kk + c4);
        }
        #pragma unroll
        for (int q = 0; q < 2; q++) {
            int e = (tid + q * 256) * 4;
            cpa16(&Bk[e], g_WkF + c * 2048 + e);
            cpa16(&Bv[e], g_WvF + c * 2048 + e);
        }
        CP_COMMIT();
    };

    float accK[2][4][4] = {};
    float accV[2][4][4] = {};

    stage(0, 0);
    #pragma unroll 1
    for (int c = 0; c < 24; c++) {
        int buf = c & 1;
        if (c + 1 < 24) { stage(c + 1, buf ^ 1); CP_WAIT1(); }
        else            { CP_WAIT0(); }
        __syncthreads();

        const float* A   = (const float*)(sm + KV_A_OFF + buf * KV_A_BUF);
        const uint4* Bk4 = (const uint4*)(sm + KV_BK_OFF + buf * KV_B_BUF);
        const uint4* Bv4 = (const uint4*)(sm + KV_BV_OFF + buf * KV_B_BUF);

        #pragma unroll
        for (int ksp = 0; ksp < 2; ksp++) {
            int k0 = ksp * 16;
            uint32_t afE[2][4], afO[2][4];
            #pragma unroll
            for (int mt = 0; mt < 2; mt++) {
                int r = m0 + mt * 16 + lr;
                afE[mt][0] = fbits(A[r * 36 + k0 + lc]);
                afE[mt][1] = fbits(A[(r + 8) * 36 + k0 + lc]);
                afE[mt][2] = fbits(A[r * 36 + k0 + lc + 4]);
                afE[mt][3] = fbits(A[(r + 8) * 36 + k0 + lc + 4]);
                afO[mt][0] = fbits(A[r * 36 + k0 + 8 + lc]);
                afO[mt][1] = fbits(A[(r + 8) * 36 + k0 + 8 + lc]);
                afO[mt][2] = fbits(A[r * 36 + k0 + 8 + lc + 4]);
                afO[mt][3] = fbits(A[(r + 8) * 36 + k0 + 8 + lc + 4]);
            }
            #pragma unroll
            for (int nt = 0; nt < 4; nt++) {
                uint4 bk = Bk4[((nh * 4 + nt) * 2 + ksp) * 32 + lane];
                uint4 bv = Bv4[((nh * 4 + nt) * 2 + ksp) * 32 + lane];
                uint32_t bkE[2] = { bk.x, bk.y }, bkO[2] = { bk.z, bk.w };
                uint32_t bvE[2] = { bv.x, bv.y }, bvO[2] = { bv.z, bv.w };
                #pragma unroll
                for (int mt = 0; mt < 2; mt++) {
                    mma8(accK[mt][nt], afE[mt], bkE);
                    mma8(accK[mt][nt], afO[mt], bkO);
                    mma8(accV[mt][nt], afE[mt], bvE);
                    mma8(accV[mt][nt], afO[mt], bvO);
                }
            }
        }
        __syncthreads();
    }

    int p  = hr0 / (N_DOM * B_ * T_);
    int r1 = hr0 % (N_DOM * B_ * T_);
    int n  = r1 / (B_ * T_);
    int r2 = r1 % (B_ * T_);
    int b  = r2 / T_, t0 = r2 % T_;
    const int nb   = n * B_ + b;
    const int sbb  = p * T_ + t0;
    const int nbh  = nb * 2 + nh;

    const int lrK   = pos8(lr);
    const int lcK0  = (2 * lc) & 3;
    const int lcK1  = (2 * lc + 1) & 3;
    const int compK = (lc >= 2);
    const int lcV   = lr & 3;
    const int compV = (lr >= 4);

    #pragma unroll
    for (int mt = 0; mt < 2; mt++) {
        int sg = (sbb + m0 + mt * 16) >> 3;
        #pragma unroll
        for (int nt = 0; nt < 4; nt++) {
            size_t base  = ((size_t)(nbh * SG_ + sg) * 4 + nt) * 64;
            size_t base2 = base + 4 * 64;
            g_k[base  + (lrK * 4 + lcK0) * 2 + compK] = accK[mt][nt][0];
            g_k[base  + (lrK * 4 + lcK1) * 2 + compK] = accK[mt][nt][1];
            g_k[base2 + (lrK * 4 + lcK0) * 2 + compK] = accK[mt][nt][2];
            g_k[base2 + (lrK * 4 + lcK1) * 2 + compK] = accK[mt][nt][3];
            g_v[base  + ((2 * lc)     * 4 + lcV) * 2 + compV] = accV[mt][nt][0];
            g_v[base  + ((2 * lc + 1) * 4 + lcV) * 2 + compV] = accV[mt][nt][1];
            g_v[base2 + ((2 * lc)     * 4 + lcV) * 2 + compV] = accV[mt][nt][2];
            g_v[base2 + ((2 * lc + 1) * 4 + lcV) * 2 + compV] = accV[mt][nt][3];
        }
    }
}

// ---------------------------------------------------------------------------
// Kernel 2: Q projection. Pair-packed frag-major B; R8 epilogue.
// ---------------------------------------------------------------------------
#define Q_A_OFF   0
#define Q_A_BUF   (128*36*4)
#define Q_B_OFF   (2*Q_A_BUF)
#define Q_B_BUF   8192
#define Q_SMEM    (Q_B_OFF + 2*Q_B_BUF)    // 53248

__global__ void __launch_bounds__(256) proj_q_mma(const float* __restrict__ x)
{
    extern __shared__ char sm[];
    const int tid  = threadIdx.x;
    const int wid  = tid >> 5;
    const int lane = tid & 31;
    const int lr = lane >> 2, lc = lane & 3;
    const int m0 = (wid & 3) * 32;
    const int nh = wid >> 2;

    const int row0 = blockIdx.x * 128;
    const int n = row0 / (B_ * T_);
    const float* Ab = x + (size_t)row0 * D_;
    const float* Wb = g_WqF + (size_t)n * I_ * D_;

    auto stage = [&](int c, int buf) {
        float* A  = (float*)(sm + Q_A_OFF + buf * Q_A_BUF);
        float* Bq = (float*)(sm + Q_B_OFF + buf * Q_B_BUF);
        int kk = c * 32;
        #pragma unroll
        for (int q = 0; q < 4; q++) {
            int e = tid + q * 256;
            int r = e >> 3, c4 = (e & 7) * 4;
            cpa16(&A[r * 36 + c4], Ab + (size_t)r * D_ + kk + c4);
        }
        #pragma unroll
        for (int q = 0; q < 2; q++) {
            int e = (tid + q * 256) * 4;
            cpa16(&Bq[e], Wb + c * 2048 + e);
        }
        CP_COMMIT();
    };

    float acc[2][4][4] = {};

    stage(0, 0);
    #pragma unroll 1
    for (int c = 0; c < 24; c++) {
        int buf = c & 1;
        if (c + 1 < 24) { stage(c + 1, buf ^ 1); CP_WAIT1(); }
        else            { CP_WAIT0(); }
        __syncthreads();

        const float* A   = (const float*)(sm + Q_A_OFF + buf * Q_A_BUF);
        const uint4* Bq4 = (const uint4*)(sm + Q_B_OFF + buf * Q_B_BUF);

        #pragma unroll
        for (int ksp = 0; ksp < 2; ksp++) {
            int k0 = ksp * 16;
            uint32_t afE[2][4], afO[2][4];
            #pragma unroll
            for (int mt = 0; mt < 2; mt++) {
                int r = m0 + mt * 16 + lr;
                afE[mt][0] = fbits(A[r * 36 + k0 + lc]);
                afE[mt][1] = fbits(A[(r + 8) * 36 + k0 + lc]);
                afE[mt][2] = fbits(A[r * 36 + k0 + lc + 4]);
                afE[mt][3] = fbits(A[(r + 8) * 36 + k0 + lc + 4]);
                afO[mt][0] = fbits(A[r * 36 + k0 + 8 + lc]);
                afO[mt][1] = fbits(A[(r + 8) * 36 + k0 + 8 + lc]);
                afO[mt][2] = fbits(A[r * 36 + k0 + 8 + lc + 4]);
                afO[mt][3] = fbits(A[(r + 8) * 36 + k0 + 8 + lc + 4]);
            }
            #pragma unroll
            for (int nt = 0; nt < 4; nt++) {
                uint4 bq = Bq4[((nh * 4 + nt) * 2 + ksp) * 32 + lane];
                uint32_t bE[2] = { bq.x, bq.y }, bO[2] = { bq.z, bq.w };
                #pragma unroll
                for (int mt = 0; mt < 2; mt++) {
                    mma8(acc[mt][nt], afE[mt], bE);
                    mma8(acc[mt][nt], afO[mt], bO);
                }
            }
        }
        __syncthreads();
    }

    const int n0 = nh * 32;
    #pragma unroll
    for (int mt = 0; mt < 2; mt++)
        #pragma unroll
        for (int nt = 0; nt < 4; nt++) {
            int row = row0 + m0 + mt * 16 + lr;
            int col = n0 + nt * 8 + lc * 2;
            *(float2*)&g_q[(size_t)row * I_ + col]       = make_float2(acc[mt][nt][0], acc[mt][nt][1]);
            *(float2*)&g_q[(size_t)(row + 8) * I_ + col] = make_float2(acc[mt][nt][2], acc[mt][nt][3]);
        }
}

// ---------------------------------------------------------------------------
// Kernel 3: flash attention (UNCHANGED from R10).
// ---------------------------------------------------------------------------
#define AT_K_BUF  8192
#define AT_V_BUF  8192
#define AT_V_OFF  (3*AT_K_BUF)             // 24576
#define AT_B_OFF  (AT_V_OFF + 3*AT_V_BUF)  // 49152
#define AT_SMEM   (AT_B_OFF + 3*256)       // 49920

__global__ void __launch_bounds__(128, 4) attn_mma(const float* __restrict__ gbias)
{
    extern __shared__ char sm[];
    const int tid  = threadIdx.x;
    const int wid  = tid >> 5;
    const int lane = tid & 31;
    const int lr = lane >> 2, lc = lane & 3;

    const int nbh = blockIdx.y;
    const int h   = nbh % H_;
    const int nb  = nbh / H_;
    const int b   = nb % B_;
    const int q0  = blockIdx.x * 128;

    const float* qg = g_q + ((size_t)nb * T_ + q0) * I_ + h * DH;
    const float* kg = g_k + (size_t)(nb * 2 + h) * SG_ * 256;
    const float* vg = g_v + (size_t)(nb * 2 + h) * SG_ * 256;
    const float* bg = gbias + b * S_;

    auto stage = [&](int c, int buf) {
        float* K  = (float*)(sm + buf * AT_K_BUF);
        float* V  = (float*)(sm + AT_V_OFF + buf * AT_V_BUF);
        float* Bb = (float*)(sm + AT_B_OFF + buf * 256);
        const float* kc = kg + (size_t)c * 2048;
        const float* vc = vg + (size_t)c * 2048;
        #pragma unroll
        for (int q = 0; q < 4; q++) {
            int e = (tid + q * 128) * 4;
            cpa16(&K[e], kc + e);
            cpa16(&V[e], vc + e);
        }
        if (tid < 16) cpa16(&Bb[tid * 4], bg + c * 64 + tid * 4);
        CP_COMMIT();
    };

    stage(0, 0);
    stage(1, 1);

    const float scale = 0.17677669529663687f * 1.4426950408889634f;
    uint32_t aQ[2][4][4];
    #pragma unroll
    for (int mt = 0; mt < 2; mt++) {
        const float* qr  = qg + (size_t)(wid * 32 + mt * 16 + lr) * I_;
        const float* qr8 = qr + 8 * I_;
        #pragma unroll
        for (int kd = 0; kd < 4; kd++) {
            aQ[mt][kd][0] = fbits(qr[kd * 8 + lc] * scale);
            aQ[mt][kd][1] = fbits(qr8[kd * 8 + lc] * scale);
            aQ[mt][kd][2] = fbits(qr[kd * 8 + lc + 4] * scale);
            aQ[mt][kd][3] = fbits(qr8[kd * 8 + lc + 4] * scale);
        }
    }

    float oacc[2][4][4] = {};
    float lsum[4] = {};

    const int NCH = S_ / 64;     // 48
    #pragma unroll 1
    for (int c = 0; c < NCH; c++) {
        if (c + 1 < NCH) CP_WAIT1(); else CP_WAIT0();
        __syncthreads();
        if (c + 2 < NCH) stage(c + 2, (c + 2) % 3);

        int buf = c % 3;
        const float2* kf = (const float2*)(sm + buf * AT_K_BUF);
        const float2* vf = (const float2*)(sm + AT_V_OFF + buf * AT_V_BUF);
        const float*  Bb = (const float*)(sm + AT_B_OFF + buf * 256);

        #pragma unroll
        for (int half = 0; half < 2; half++) {
            const int stb = half * 4;

            float sc[2][4][4] = {};
            #pragma unroll
            for (int kd = 0; kd < 4; kd++) {
                #pragma unroll
                for (int st = 0; st < 4; st++) {
                    float2 kv = kf[((stb + st) * 4 + kd) * 32 + lane];
                    uint32_t bb[2] = { fbits(kv.x), fbits(kv.y) };
                    mma8(sc[0][st], aQ[0][kd], bb);
                    mma8(sc[1][st], aQ[1][kd], bb);
                }
            }

            #pragma unroll
            for (int st = 0; st < 4; st++) {
                float2 bv = *(const float2*)&Bb[(stb + st) * 8 + 2 * lc];
                #pragma unroll
                for (int mt = 0; mt < 2; mt++) {
                    sc[mt][st][0] = exp2f(sc[mt][st][0] + bv.x); lsum[mt * 2]     += sc[mt][st][0];
                    sc[mt][st][1] = exp2f(sc[mt][st][1] + bv.y); lsum[mt * 2]     += sc[mt][st][1];
                    sc[mt][st][2] = exp2f(sc[mt][st][2] + bv.x); lsum[mt * 2 + 1] += sc[mt][st][2];
                    sc[mt][st][3] = exp2f(sc[mt][st][3] + bv.y); lsum[mt * 2 + 1] += sc[mt][st][3];
                }
            }

            #pragma unroll
            for (int st = 0; st < 4; st++) {
                uint32_t aP0[4] = { fbits(sc[0][st][0]), fbits(sc[0][st][2]),
                                    fbits(sc[0][st][1]), fbits(sc[0][st][3]) };
                uint32_t aP1[4] = { fbits(sc[1][st][0]), fbits(sc[1][st][2]),
                                    fbits(sc[1][st][1]), fbits(sc[1][st][3]) };
                #pragma unroll
                for (int dt = 0; dt < 4; dt++) {
                    float2 vv = vf[((stb + st) * 4 + dt) * 32 + lane];
                    uint32_t bb[2] = { fbits(vv.x), fbits(vv.y) };
                    mma8(oacc[0][dt], aP0, bb);
                    mma8(oacc[1][dt], aP1, bb);
                }
            }
        }
    }

    const unsigned FULL = 0xffffffffu;
    #pragma unroll
    for (int i = 0; i < 4; i++) {
        lsum[i] += __shfl_xor_sync(FULL, lsum[i], 1);
        lsum[i] += __shfl_xor_sync(FULL, lsum[i], 2);
        lsum[i] = 1.0f / lsum[i];
    }

    #pragma unroll
    for (int mt = 0; mt < 2; mt++) {
        int row = nb * T_ + q0 + wid * 32 + mt * 16 + lr;
        #pragma unroll
        for (int dt = 0; dt < 4; dt++) {
            int col = h * DH + dt * 8 + 2 * lc;
            *(float2*)&g_o[(size_t)row * I_ + col] =
                make_float2(oacc[mt][dt][0] * lsum[mt * 2], oacc[mt][dt][1] * lsum[mt * 2]);
            *(float2*)&g_o[(size_t)(row + 8) * I_ + col] =
                make_float2(oacc[mt][dt][2] * lsum[mt * 2 + 1], oacc[mt][dt][3] * lsum[mt * 2 + 1]);
        }
    }
}

// ---------------------------------------------------------------------------
// Kernel 4: out projection + residual (UNCHANGED R8/R10)
// ---------------------------------------------------------------------------
#define O_A_OFF  0
#define O_A_SZ   (128*68*4)
#define O_B_OFF  O_A_SZ
#define O_SMEM   (2*O_A_SZ)

__global__ void __launch_bounds__(256) outproj_mma(
    const float* __restrict__ x, float* __restrict__ out)
{
    extern __shared__ char sm[];
    const int tid  = threadIdx.x;
    const int wid  = tid >> 5;
    const int lane = tid & 31;
    const int lr = lane >> 2, lc = lane & 3;
    const int m0 = (wid & 3) * 32;
    const int n0 = (wid >> 2) * 64;

    const int row0 = blockIdx.x * 128;
    const int col0 = blockIdx.y * 128;
    const int n = row0 / (B_ * T_);

    float* A = (float*)(sm + O_A_OFF);
    float* B = (float*)(sm + O_B_OFF);

    #pragma unroll
    for (int q = 0; q < 8; q++) {
        int e = tid + q * 256;
        int r = e >> 4, c4 = (e & 15) * 4;
        cpa16(&A[r * 68 + c4], g_o + (size_t)(row0 + r) * I_ + c4);
    }
    #pragma unroll
    for (int q = 0; q < 8; q++) {
        int e = tid + q * 256;
        int r = e >> 4, c4 = (e & 15) * 4;
        cpa16(&B[r * 68 + c4], g_WoT + ((size_t)n * D_ + col0 + r) * I_ + c4);
    }
    CP_COMMIT();
    CP_WAIT0();
    __syncthreads();

    float acc[2][8][4] = {};
    #pragma unroll
    for (int ks = 0; ks < 8; ks++) {
        int k0 = ks * 8;
        uint32_t af[2][4];
        #pragma unroll
        for (int mt = 0; mt < 2; mt++) {
            int r = m0 + mt * 16 + lr;
            af[mt][0] = fbits(A[r * 68 + k0 + lc]);
            af[mt][1] = fbits(A[(r + 8) * 68 + k0 + lc]);
            af[mt][2] = fbits(A[r * 68 + k0 + lc + 4]);
            af[mt][3] = fbits(A[(r + 8) * 68 + k0 + lc + 4]);
        }
        #pragma unroll
        for (int nt = 0; nt < 8; nt++) {
            int nn = n0 + nt * 8 + lr;
            uint32_t bf[2];
            bf[0] = fbits(B[nn * 68 + k0 + lc]);
            bf[1] = fbits(B[nn * 68 + k0 + lc + 4]);
            mma8(acc[0][nt], af[0], bf);
            mma8(acc[1][nt], af[1], bf);
        }
    }

    #pragma unroll
    for (int mt = 0; mt < 2; mt++)
        #pragma unroll
        for (int nt = 0; nt < 8; nt++) {
            int row = row0 + m0 + mt * 16 + lr;
            int col = col0 + n0 + nt * 8 + lc * 2;
            float2 x0 = *(const float2*)&x[(size_t)row * D_ + col];
            float2 x1 = *(const float2*)&x[(size_t)(row + 8) * D_ + col];
            *(float2*)&out[(size_t)row * D_ + col] =
                make_float2(acc[mt][nt][0] + x0.x, acc[mt][nt][1] + x0.y);
            *(float2*)&out[(size_t)(row + 8) * D_ + col] =
                make_float2(acc[mt][nt][2] + x1.x, acc[mt][nt][3] + x1.y);
        }
}

// ---------------------------------------------------------------------------
// Kernel 5: LayerNorm in place on d_out. (UNCHANGED)
// ---------------------------------------------------------------------------
__global__ void __launch_bounds__(256) ln_kernel(
    float* __restrict__ y,
    const float* __restrict__ gamma,
    const float* __restrict__ beta)
{
    const int row = blockIdx.x;
    const int n   = row / (B_ * T_);
    float* yr = y + (size_t)row * D_;
    const int tid = threadIdx.x;

    float v[3];
    float s = 0.0f, ss = 0.0f;
    #pragma unroll
    for (int i = 0; i < 3; i++) {
        v[i] = yr[tid + i * 256];
        s  += v[i];
        ss += v[i] * v[i];
    }
    const unsigned FULL = 0xffffffffu;
    #pragma unroll
    for (int off = 16; off; off >>= 1) {
        s  += __shfl_xor_sync(FULL, s,  off);
        ss += __shfl_xor_sync(FULL, ss, off);
    }
    __shared__ float rs[8], rss[8];
    int wid = tid >> 5, lane = tid & 31;
    if (!lane) { rs[wid] = s; rss[wid] = ss; }
    __syncthreads();
    if (tid == 0) {
        float a = 0.0f, c = 0.0f;
        #pragma unroll
        for (int w = 0; w < 8; w++) { a += rs[w]; c += rss[w]; }
        rs[0] = a; rss[0] = c;
    }
    __syncthreads();
    float mu   = rs[0] * (1.0f / D_);
    float var  = rss[0] * (1.0f / D_) - mu * mu;
    float rstd = rsqrtf(var + 1e-5f);
    #pragma unroll
    for (int i = 0; i < 3; i++) {
        int d = tid + i * 256;
        yr[d] = (v[i] - mu) * rstd * gamma[n * D_ + d] + beta[n * D_ + d];
    }
}

// ---------------------------------------------------------------------------
extern "C" void kernel_launch(void* const* d_in, const int* in_sizes, int n_in,
                              void* d_out, int out_size)
{
    const float* x     = (const float*)d_in[0];
    const float* hist  = (const float*)d_in[1];
    const int*   mask  = (const int*)  d_in[2];
    const float* Wq    = (const float*)d_in[3];
    const float* Wk    = (const float*)d_in[4];
    const float* Wv    = (const float*)d_in[5];
    const float* Wo    = (const float*)d_in[6];
    const float* gamma = (const float*)d_in[7];
    const float* beta  = (const float*)d_in[8];
    float* out = (float*)d_out;

    cudaFuncSetAttribute(proj_kv_mma, cudaFuncAttributeMaxDynamicSharedMemorySize, KV_SMEM);
    cudaFuncSetAttribute(proj_q_mma,  cudaFuncAttributeMaxDynamicSharedMemorySize, Q_SMEM);
    cudaFuncSetAttribute(attn_mma,    cudaFuncAttributeMaxDynamicSharedMemorySize, AT_SMEM);
    cudaFuncSetAttribute(outproj_mma, cudaFuncAttributeMaxDynamicSharedMemorySize, O_SMEM);

    prep_weights<<<(N_DOM * I_ * D_ + 255) / 256, 256>>>(Wk, Wv, Wq, Wo, mask);

    proj_kv_mma<<<NBS / 128, 256, KV_SMEM>>>(hist);
    proj_q_mma <<<NBT / 128, 256, Q_SMEM>>>(x);

    float* bias_dev = nullptr;
    cudaGetSymbolAddress((void**)&bias_dev, g_bias);

    dim3 ag(T_ / 128, N_DOM * B_ * H_);
    attn_mma<<<ag, 128, AT_SMEM>>>(bias_dev);

    dim3 og(NBT / 128, D_ / 128);
    outproj_mma<<<og, 256, O_SMEM>>>(x, out);

    ln_kernel<<<NBT, 256>>>(out, gamma, beta);
}

// round 12
// speedup vs baseline: 1.0863x; 1.0863x over previous
#include <cuda_runtime.h>
#include <cstdint>

#define N_DOM 6
#define B_    4
#define T_    1024
#define D_    768
#define P_    3
#define H_    2
#define DH    32
#define I_    64
#define S_    (P_*T_)          // 3072
#define NBT   (N_DOM*B_*T_)    // 24576
#define NBS   (N_DOM*B_*S_)    // 73728
#define SG_   (S_/8)           // 384 key-groups per (nb,h)
#define NSPLIT 3
#define NCHP  (S_/64/NSPLIT)   // 16 chunks per split

// Scratch (allocation-free rule: device globals)
__device__ float g_q[NBT*I_];
__device__ float g_k[NBS*I_];   // fragment-major: [nbh][sg][kd][lane]{x,y}
__device__ float g_v[NBS*I_];   // fragment-major: [nbh][sg][dt][lane]{x,y}
__device__ float g_o[NBT*I_];
__device__ float g_op[NSPLIT*NBT*I_];   // attention partials (unnormalized)
__device__ float g_lp[NSPLIT*NBT*2];    // partial row sums per (row, head)
__device__ float g_WkT[I_*D_];
__device__ float g_WvT[I_*D_];
__device__ float g_WqT[N_DOM*I_*D_];
__device__ float g_WoT[N_DOM*D_*I_];
__device__ float g_bias[B_*S_];  // (1-mask)*-10000*log2(e), pos8-permuted per 8-group

// ---------------------------------------------------------------------------
// helpers
// ---------------------------------------------------------------------------
__device__ __forceinline__ uint32_t smem_u32(const void* p) {
    uint32_t a;
    asm("{ .reg .u64 t; cvta.to.shared.u64 t, %1; cvt.u32.u64 %0, t; }" : "=r"(a) : "l"(p));
    return a;
}
__device__ __forceinline__ void cpa16(void* s, const void* g) {
    uint32_t sa = smem_u32(s);
    asm volatile("cp.async.cg.shared.global [%0], [%1], 16;" :: "r"(sa), "l"(g) : "memory");
}
#define CP_COMMIT() asm volatile("cp.async.commit_group;" ::: "memory")
#define CP_WAIT0()  asm volatile("cp.async.wait_group 0;" ::: "memory")
#define CP_WAIT1()  asm volatile("cp.async.wait_group 1;" ::: "memory")

__device__ __forceinline__ float to_tf32_rna(float x) {
    uint32_t u;
    asm("cvt.rna.tf32.f32 %0, %1;" : "=r"(u) : "f"(x));
    return __uint_as_float(u);
}
__device__ __forceinline__ uint32_t fbits(float x) { return __float_as_uint(x); }

__device__ __forceinline__ void mma8(float* c, const uint32_t* a, const uint32_t* b) {
    asm volatile(
        "mma.sync.aligned.m16n8k8.row.col.f32.tf32.tf32.f32 "
        "{%0,%1,%2,%3}, {%4,%5,%6,%7}, {%8,%9}, {%0,%1,%2,%3};"
        : "+f"(c[0]), "+f"(c[1]), "+f"(c[2]), "+f"(c[3])
        : "r"(a[0]), "r"(a[1]), "r"(a[2]), "r"(a[3]), "r"(b[0]), "r"(b[1]));
}

// permutation within 8-groups: logical r -> stored pos (pairs (r, r+4) adjacent)
__device__ __forceinline__ int pos8(int r) { return (r < 4) ? 2 * r : 2 * (r - 4) + 1; }

// ---------------------------------------------------------------------------
// Kernel 0: weight transpose (+tf32 round) and permuted bias table (log2 dom)
// ---------------------------------------------------------------------------
__global__ void __launch_bounds__(256) transpose_weights(
    const float* __restrict__ Wk, const float* __restrict__ Wv,
    const float* __restrict__ Wq, const float* __restrict__ Wo,
    const int* __restrict__ mask)
{
    int idx = blockIdx.x * 256 + threadIdx.x;
    if (idx < I_ * D_) {
        int i = idx / D_, d = idx % D_;
        g_WkT[idx] = to_tf32_rna(Wk[d * I_ + i]);
        g_WvT[idx] = to_tf32_rna(Wv[d * I_ + i]);
    }
    if (idx < N_DOM * I_ * D_) {
        int n = idx / (I_ * D_), r = idx % (I_ * D_);
        int i = r / D_, d = r % D_;
        g_WqT[idx] = to_tf32_rna(Wq[((size_t)n * D_ + d) * I_ + i]);
    }
    if (idx < N_DOM * D_ * I_) {
        int n = idx / (D_ * I_), r = idx % (D_ * I_);
        int d = r / I_, i = r % I_;
        g_WoT[idx] = to_tf32_rna(Wo[((size_t)n * I_ + i) * D_ + d]);
    }
    if (idx < B_ * S_) {
        int b = idx / S_, s = idx % S_;
        float v = (1.0f - (float)mask[b * T_ + (s % T_)]) * -10000.0f
                  * 1.4426950408889634f;
        g_bias[b * S_ + (s & ~7) + pos8(s & 7)] = v;   // key s stored at pos8(s)
    }
}

// ---------------------------------------------------------------------------
// Kernel 1: K+V projection. Epilogue writes FRAGMENT-MAJOR K and V. (R10)
// ---------------------------------------------------------------------------
#define KV_A_OFF   0
#define KV_A_BUF   (128*36*4)
#define KV_BK_OFF  (2*KV_A_BUF)
#define KV_B_BUF   (64*36*4)
#define KV_BV_OFF  (KV_BK_OFF + 2*KV_B_BUF)
#define KV_SMEM    (KV_BV_OFF + 2*KV_B_BUF)

__global__ void __launch_bounds__(256) proj_kv_mma(const float* __restrict__ hist)
{
    extern __shared__ char sm[];
    const int tid  = threadIdx.x;
    const int wid  = tid >> 5;
    const int lane = tid & 31;
    const int lr = lane >> 2, lc = lane & 3;
    const int m0 = (wid & 3) * 32;
    const int n0 = (wid >> 2) * 32;

    const int hr0 = blockIdx.x * 128;
    const float* Ab = hist + (size_t)hr0 * D_;

    auto stage = [&](int c, int buf) {
        int kk = c * 32;
        float* A  = (float*)(sm + KV_A_OFF  + buf * KV_A_BUF);
        float* Bk = (float*)(sm + KV_BK_OFF + buf * KV_B_BUF);
        float* Bv = (float*)(sm + KV_BV_OFF + buf * KV_B_BUF);
        #pragma unroll
        for (int q = 0; q < 4; q++) {
            int e = tid + q * 256;
            int r = e >> 3, c4 = (e & 7) * 4;
            cpa16(&A[r * 36 + c4], Ab + (size_t)r * D_ + kk + c4);
        }
        #pragma unroll
        for (int q = 0; q < 2; q++) {
            int e = tid + q * 256;
            int r = e >> 3, c4 = (e & 7) * 4;
            cpa16(&Bk[r * 36 + c4], g_WkT + (size_t)r * D_ + kk + c4);
            cpa16(&Bv[r * 36 + c4], g_WvT + (size_t)r * D_ + kk + c4);
        }
        CP_COMMIT();
    };

    float accK[2][4][4] = {};
    float accV[2][4][4] = {};

    stage(0, 0);
    #pragma unroll 1
    for (int c = 0; c < 24; c++) {
        int buf = c & 1;
        if (c + 1 < 24) { stage(c + 1, buf ^ 1); CP_WAIT1(); }
        else            { CP_WAIT0(); }
        __syncthreads();

        const float* A  = (const float*)(sm + KV_A_OFF + buf * KV_A_BUF);
        const float* Bk = (const float*)(sm + KV_BK_OFF + buf * KV_B_BUF);
        const float* Bv = (const float*)(sm + KV_BV_OFF + buf * KV_B_BUF);

        #pragma unroll
        for (int ks = 0; ks < 4; ks++) {
            int k0 = ks * 8;
            uint32_t af[2][4];
            #pragma unroll
            for (int mt = 0; mt < 2; mt++) {
                int r = m0 + mt * 16 + lr;
                af[mt][0] = fbits(A[r * 36 + k0 + lc]);
                af[mt][1] = fbits(A[(r + 8) * 36 + k0 + lc]);
                af[mt][2] = fbits(A[r * 36 + k0 + lc + 4]);
                af[mt][3] = fbits(A[(r + 8) * 36 + k0 + lc + 4]);
            }
            uint32_t bk[4][2], bv[4][2];
            #pragma unroll
            for (int nt = 0; nt < 4; nt++) {
                int nn = n0 + nt * 8 + lr;
                bk[nt][0] = fbits(Bk[nn * 36 + k0 + lc]);
                bk[nt][1] = fbits(Bk[nn * 36 + k0 + lc + 4]);
                bv[nt][0] = fbits(Bv[nn * 36 + k0 + lc]);
                bv[nt][1] = fbits(Bv[nn * 36 + k0 + lc + 4]);
            }
            #pragma unroll
            for (int mt = 0; mt < 2; mt++)
                #pragma unroll
                for (int nt = 0; nt < 4; nt++) {
                    mma8(accK[mt][nt], af[mt], bk[nt]);
                    mma8(accV[mt][nt], af[mt], bv[nt]);
                }
        }
        __syncthreads();
    }

    int p  = hr0 / (N_DOM * B_ * T_);
    int r1 = hr0 % (N_DOM * B_ * T_);
    int n  = r1 / (B_ * T_);
    int r2 = r1 % (B_ * T_);
    int b  = r2 / T_, t0 = r2 % T_;
    const int nb   = n * B_ + b;
    const int sbb  = p * T_ + t0;
    const int head = n0 >> 5;
    const int nbh  = nb * 2 + head;

    const int lrK   = pos8(lr);
    const int lcK0  = (2 * lc) & 3;
    const int lcK1  = (2 * lc + 1) & 3;
    const int compK = (lc >= 2);
    const int lcV   = lr & 3;
    const int compV = (lr >= 4);

    #pragma unroll
    for (int mt = 0; mt < 2; mt++) {
        int sg = (sbb + m0 + mt * 16) >> 3;
        #pragma unroll
        for (int nt = 0; nt < 4; nt++) {
            size_t base  = ((size_t)(nbh * SG_ + sg) * 4 + nt) * 64;
            size_t base2 = base + 4 * 64;
            g_k[base  + (lrK * 4 + lcK0) * 2 + compK] = accK[mt][nt][0];
            g_k[base  + (lrK * 4 + lcK1) * 2 + compK] = accK[mt][nt][1];
            g_k[base2 + (lrK * 4 + lcK0) * 2 + compK] = accK[mt][nt][2];
            g_k[base2 + (lrK * 4 + lcK1) * 2 + compK] = accK[mt][nt][3];
            g_v[base  + ((2 * lc)     * 4 + lcV) * 2 + compV] = accV[mt][nt][0];
            g_v[base  + ((2 * lc + 1) * 4 + lcV) * 2 + compV] = accV[mt][nt][1];
            g_v[base2 + ((2 * lc)     * 4 + lcV) * 2 + compV] = accV[mt][nt][2];
            g_v[base2 + ((2 * lc + 1) * 4 + lcV) * 2 + compV] = accV[mt][nt][3];
        }
    }
}

// ---------------------------------------------------------------------------
// Kernel 2: Q projection (R10)
// ---------------------------------------------------------------------------
#define Q_A_OFF   0
#define Q_A_BUF   (128*36*4)
#define Q_B_OFF   (2*Q_A_BUF)
#define Q_B_BUF   (64*36*4)
#define Q_SMEM    (Q_B_OFF + 2*Q_B_BUF)

__global__ void __launch_bounds__(256) proj_q_mma(const float* __restrict__ x)
{
    extern __shared__ char sm[];
    const int tid  = threadIdx.x;
    const int wid  = tid >> 5;
    const int lane = tid & 31;
    const int lr = lane >> 2, lc = lane & 3;
    const int m0 = (wid & 3) * 32;
    const int n0 = (wid >> 2) * 32;

    const int row0 = blockIdx.x * 128;
    const int n = row0 / (B_ * T_);
    const float* Ab = x + (size_t)row0 * D_;
    const float* Wb = g_WqT + (size_t)n * I_ * D_;

    auto stage = [&](int c, int buf) {
        int kk = c * 32;
        float* A  = (float*)(sm + Q_A_OFF + buf * Q_A_BUF);
        float* Bq = (float*)(sm + Q_B_OFF + buf * Q_B_BUF);
        #pragma unroll
        for (int q = 0; q < 4; q++) {
            int e = tid + q * 256;
            int r = e >> 3, c4 = (e & 7) * 4;
            cpa16(&A[r * 36 + c4], Ab + (size_t)r * D_ + kk + c4);
        }
        #pragma unroll
        for (int q = 0; q < 2; q++) {
            int e = tid + q * 256;
            int r = e >> 3, c4 = (e & 7) * 4;
            cpa16(&Bq[r * 36 + c4], Wb + (size_t)r * D_ + kk + c4);
        }
        CP_COMMIT();
    };

    float acc[2][4][4] = {};

    stage(0, 0);
    #pragma unroll 1
    for (int c = 0; c < 24; c++) {
        int buf = c & 1;
        if (c + 1 < 24) { stage(c + 1, buf ^ 1); CP_WAIT1(); }
        else            { CP_WAIT0(); }
        __syncthreads();

        const float* A  = (const float*)(sm + Q_A_OFF + buf * Q_A_BUF);
        const float* Bq = (const float*)(sm + Q_B_OFF + buf * Q_B_BUF);

        #pragma unroll
        for (int ks = 0; ks < 4; ks++) {
            int k0 = ks * 8;
            uint32_t af[2][4];
            #pragma unroll
            for (int mt = 0; mt < 2; mt++) {
                int r = m0 + mt * 16 + lr;
                af[mt][0] = fbits(A[r * 36 + k0 + lc]);
                af[mt][1] = fbits(A[(r + 8) * 36 + k0 + lc]);
                af[mt][2] = fbits(A[r * 36 + k0 + lc + 4]);
                af[mt][3] = fbits(A[(r + 8) * 36 + k0 + lc + 4]);
            }
            uint32_t bq[4][2];
            #pragma unroll
            for (int nt = 0; nt < 4; nt++) {
                int nn = n0 + nt * 8 + lr;
                bq[nt][0] = fbits(Bq[nn * 36 + k0 + lc]);
                bq[nt][1] = fbits(Bq[nn * 36 + k0 + lc + 4]);
            }
            #pragma unroll
            for (int mt = 0; mt < 2; mt++)
                #pragma unroll
                for (int nt = 0; nt < 4; nt++)
                    mma8(acc[mt][nt], af[mt], bq[nt]);
        }
        __syncthreads();
    }

    #pragma unroll
    for (int mt = 0; mt < 2; mt++)
        #pragma unroll
        for (int nt = 0; nt < 4; nt++) {
            int row = row0 + m0 + mt * 16 + lr;
            int col = n0 + nt * 8 + lc * 2;
            *(float2*)&g_q[(size_t)row * I_ + col]       = make_float2(acc[mt][nt][0], acc[mt][nt][1]);
            *(float2*)&g_q[(size_t)(row + 8) * I_ + col] = make_float2(acc[mt][nt][2], acc[mt][nt][3]);
        }
}

// ---------------------------------------------------------------------------
// Kernel 3: flash attention, 3-way split over keys (additive partials thanks
// to no-max exp2 softmax). Structure otherwise identical to R10.
// ---------------------------------------------------------------------------
#define AT_K_BUF  8192
#define AT_V_BUF  8192
#define AT_V_OFF  (3*AT_K_BUF)             // 24576
#define AT_B_OFF  (AT_V_OFF + 3*AT_V_BUF)  // 49152
#define AT_SMEM   (AT_B_OFF + 3*256)       // 49920

__global__ void __launch_bounds__(128, 4) attn_mma(const float* __restrict__ gbias)
{
    extern __shared__ char sm[];
    const int tid  = threadIdx.x;
    const int wid  = tid >> 5;
    const int lane = tid & 31;
    const int lr = lane >> 2, lc = lane & 3;

    const int nbh = blockIdx.y;
    const int h   = nbh % H_;
    const int nb  = nbh / H_;
    const int b   = nb % B_;
    const int q0  = blockIdx.x * 128;
    const int sp  = blockIdx.z;
    const int cb  = sp * NCHP;

    const float* qg = g_q + ((size_t)nb * T_ + q0) * I_ + h * DH;
    const float* kg = g_k + (size_t)(nb * 2 + h) * SG_ * 256;
    const float* vg = g_v + (size_t)(nb * 2 + h) * SG_ * 256;
    const float* bg = gbias + b * S_;

    auto stage = [&](int c, int buf) {
        float* K  = (float*)(sm + buf * AT_K_BUF);
        float* V  = (float*)(sm + AT_V_OFF + buf * AT_V_BUF);
        float* Bb = (float*)(sm + AT_B_OFF + buf * 256);
        const float* kc = kg + (size_t)(cb + c) * 2048;
        const float* vc = vg + (size_t)(cb + c) * 2048;
        #pragma unroll
        for (int q = 0; q < 4; q++) {
            int e = (tid + q * 128) * 4;
            cpa16(&K[e], kc + e);
            cpa16(&V[e], vc + e);
        }
        if (tid < 16) cpa16(&Bb[tid * 4], bg + (cb + c) * 64 + tid * 4);
        CP_COMMIT();
    };

    stage(0, 0);
    stage(1, 1);

    const float scale = 0.17677669529663687f * 1.4426950408889634f;
    uint32_t aQ[2][4][4];
    #pragma unroll
    for (int mt = 0; mt < 2; mt++) {
        const float* qr  = qg + (size_t)(wid * 32 + mt * 16 + lr) * I_;
        const float* qr8 = qr + 8 * I_;
        #pragma unroll
        for (int kd = 0; kd < 4; kd++) {
            aQ[mt][kd][0] = fbits(qr[kd * 8 + lc] * scale);
            aQ[mt][kd][1] = fbits(qr8[kd * 8 + lc] * scale);
            aQ[mt][kd][2] = fbits(qr[kd * 8 + lc + 4] * scale);
            aQ[mt][kd][3] = fbits(qr8[kd * 8 + lc + 4] * scale);
        }
    }

    float oacc[2][4][4] = {};
    float lsum[4] = {};

    #pragma unroll 1
    for (int c = 0; c < NCHP; c++) {
        if (c + 1 < NCHP) CP_WAIT1(); else CP_WAIT0();
        __syncthreads();
        if (c + 2 < NCHP) stage(c + 2, (c + 2) % 3);

        int buf = c % 3;
        const float2* kf = (const float2*)(sm + buf * AT_K_BUF);
        const float2* vf = (const float2*)(sm + AT_V_OFF + buf * AT_V_BUF);
        const float*  Bb = (const float*)(sm + AT_B_OFF + buf * 256);

        #pragma unroll
        for (int half = 0; half < 2; half++) {
            const int stb = half * 4;

            float sc[2][4][4] = {};
            #pragma unroll
            for (int kd = 0; kd < 4; kd++) {
                #pragma unroll
                for (int st = 0; st < 4; st++) {
                    float2 kv = kf[((stb + st) * 4 + kd) * 32 + lane];
                    uint32_t bb[2] = { fbits(kv.x), fbits(kv.y) };
                    mma8(sc[0][st], aQ[0][kd], bb);
                    mma8(sc[1][st], aQ[1][kd], bb);
                }
            }

            #pragma unroll
            for (int st = 0; st < 4; st++) {
                float2 bv = *(const float2*)&Bb[(stb + st) * 8 + 2 * lc];
                #pragma unroll
                for (int mt = 0; mt < 2; mt++) {
                    sc[mt][st][0] = exp2f(sc[mt][st][0] + bv.x); lsum[mt * 2]     += sc[mt][st][0];
                    sc[mt][st][1] = exp2f(sc[mt][st][1] + bv.y); lsum[mt * 2]     += sc[mt][st][1];
                    sc[mt][st][2] = exp2f(sc[mt][st][2] + bv.x); lsum[mt * 2 + 1] += sc[mt][st][2];
                    sc[mt][st][3] = exp2f(sc[mt][st][3] + bv.y); lsum[mt * 2 + 1] += sc[mt][st][3];
                }
            }

            #pragma unroll
            for (int st = 0; st < 4; st++) {
                uint32_t aP0[4] = { fbits(sc[0][st][0]), fbits(sc[0][st][2]),
                                    fbits(sc[0][st][1]), fbits(sc[0][st][3]) };
                uint32_t aP1[4] = { fbits(sc[1][st][0]), fbits(sc[1][st][2]),
                                    fbits(sc[1][st][1]), fbits(sc[1][st][3]) };
                #pragma unroll
                for (int dt = 0; dt < 4; dt++) {
                    float2 vv = vf[((stb + st) * 4 + dt) * 32 + lane];
                    uint32_t bb[2] = { fbits(vv.x), fbits(vv.y) };
                    mma8(oacc[0][dt], aP0, bb);
                    mma8(oacc[1][dt], aP1, bb);
                }
            }
        }
    }

    const unsigned FULL = 0xffffffffu;
    #pragma unroll
    for (int i = 0; i < 4; i++) {
        lsum[i] += __shfl_xor_sync(FULL, lsum[i], 1);
        lsum[i] += __shfl_xor_sync(FULL, lsum[i], 2);
    }

    // ---- write RAW partials (no normalization) ----
    float* op = g_op + (size_t)sp * NBT * I_;
    #pragma unroll
    for (int mt = 0; mt < 2; mt++) {
        int row = nb * T_ + q0 + wid * 32 + mt * 16 + lr;
        #pragma unroll
        for (int dt = 0; dt < 4; dt++) {
            int col = h * DH + dt * 8 + 2 * lc;
            *(float2*)&op[(size_t)row * I_ + col] =
                make_float2(oacc[mt][dt][0], oacc[mt][dt][1]);
            *(float2*)&op[(size_t)(row + 8) * I_ + col] =
                make_float2(oacc[mt][dt][2], oacc[mt][dt][3]);
        }
        if (lc == 0) {
            g_lp[((size_t)sp * NBT + row) * 2 + h]     = lsum[mt * 2];
            g_lp[((size_t)sp * NBT + row + 8) * 2 + h] = lsum[mt * 2 + 1];
        }
    }
}

// ---------------------------------------------------------------------------
// Kernel 3b: combine split partials: g_o = (sum_p op) / (sum_p lp)
// ---------------------------------------------------------------------------
__global__ void __launch_bounds__(256) attn_combine()
{
    int idx = blockIdx.x * 256 + threadIdx.x;    // over NBT*16 float4s
    int row = idx >> 4;
    int c4  = idx & 15;
    int h   = c4 >> 3;

    size_t eo = (size_t)row * I_ + c4 * 4;
    float4 a0 = *(const float4*)&g_op[eo];
    float4 a1 = *(const float4*)&g_op[(size_t)NBT * I_ + eo];
    float4 a2 = *(const float4*)&g_op[(size_t)2 * NBT * I_ + eo];
    float l = g_lp[(size_t)row * 2 + h]
            + g_lp[((size_t)NBT + row) * 2 + h]
            + g_lp[((size_t)2 * NBT + row) * 2 + h];
    float inv = 1.0f / l;
    *(float4*)&g_o[eo] = make_float4((a0.x + a1.x + a2.x) * inv,
                                     (a0.y + a1.y + a2.y) * inv,
                                     (a0.z + a1.z + a2.z) * inv,
                                     (a0.w + a1.w + a2.w) * inv);
}

// ---------------------------------------------------------------------------
// Kernel 4: out projection + residual (R10)
// ---------------------------------------------------------------------------
#define O_A_OFF  0
#define O_A_SZ   (128*68*4)
#define O_B_OFF  O_A_SZ
#define O_SMEM   (2*O_A_SZ)

__global__ void __launch_bounds__(256) outproj_mma(
    const float* __restrict__ x, float* __restrict__ out)
{
    extern __shared__ char sm[];
    const int tid  = threadIdx.x;
    const int wid  = tid >> 5;
    const int lane = tid & 31;
    const int lr = lane >> 2, lc = lane & 3;
    const int m0 = (wid & 3) * 32;
    const int n0 = (wid >> 2) * 64;

    const int row0 = blockIdx.x * 128;
    const int col0 = blockIdx.y * 128;
    const int n = row0 / (B_ * T_);

    float* A = (float*)(sm + O_A_OFF);
    float* B = (float*)(sm + O_B_OFF);

    #pragma unroll
    for (int q = 0; q < 8; q++) {
        int e = tid + q * 256;
        int r = e >> 4, c4 = (e & 15) * 4;
        cpa16(&A[r * 68 + c4], g_o + (size_t)(row0 + r) * I_ + c4);
    }
    #pragma unroll
    for (int q = 0; q < 8; q++) {
        int e = tid + q * 256;
        int r = e >> 4, c4 = (e & 15) * 4;
        cpa16(&B[r * 68 + c4], g_WoT + ((size_t)n * D_ + col0 + r) * I_ + c4);
    }
    CP_COMMIT();
    CP_WAIT0();
    __syncthreads();

    float acc[2][8][4] = {};
    #pragma unroll
    for (int ks = 0; ks < 8; ks++) {
        int k0 = ks * 8;
        uint32_t af[2][4];
        #pragma unroll
        for (int mt = 0; mt < 2; mt++) {
            int r = m0 + mt * 16 + lr;
            af[mt][0] = fbits(A[r * 68 + k0 + lc]);
            af[mt][1] = fbits(A[(r + 8) * 68 + k0 + lc]);
            af[mt][2] = fbits(A[r * 68 + k0 + lc + 4]);
            af[mt][3] = fbits(A[(r + 8) * 68 + k0 + lc + 4]);
        }
        #pragma unroll
        for (int nt = 0; nt < 8; nt++) {
            int nn = n0 + nt * 8 + lr;
            uint32_t bf[2];
            bf[0] = fbits(B[nn * 68 + k0 + lc]);
            bf[1] = fbits(B[nn * 68 + k0 + lc + 4]);
            mma8(acc[0][nt], af[0], bf);
            mma8(acc[1][nt], af[1], bf);
        }
    }

    #pragma unroll
    for (int mt = 0; mt < 2; mt++)
        #pragma unroll
        for (int nt = 0; nt < 8; nt++) {
            int row = row0 + m0 + mt * 16 + lr;
            int col = col0 + n0 + nt * 8 + lc * 2;
            float2 x0 = *(const float2*)&x[(size_t)row * D_ + col];
            float2 x1 = *(const float2*)&x[(size_t)(row + 8) * D_ + col];
            *(float2*)&out[(size_t)row * D_ + col] =
                make_float2(acc[mt][nt][0] + x0.x, acc[mt][nt][1] + x0.y);
            *(float2*)&out[(size_t)(row + 8) * D_ + col] =
                make_float2(acc[mt][nt][2] + x1.x, acc[mt][nt][3] + x1.y);
        }
}

// ---------------------------------------------------------------------------
// Kernel 5: LayerNorm in place on d_out. (R10)
// ---------------------------------------------------------------------------
__global__ void __launch_bounds__(256) ln_kernel(
    float* __restrict__ y,
    const float* __restrict__ gamma,
    const float* __restrict__ beta)
{
    const int row = blockIdx.x;
    const int n   = row / (B_ * T_);
    float* yr = y + (size_t)row * D_;
    const int tid = threadIdx.x;

    float v[3];
    float s = 0.0f, ss = 0.0f;
    #pragma unroll
    for (int i = 0; i < 3; i++) {
        v[i] = yr[tid + i * 256];
        s  += v[i];
        ss += v[i] * v[i];
    }
    const unsigned FULL = 0xffffffffu;
    #pragma unroll
    for (int off = 16; off; off >>= 1) {
        s  += __shfl_xor_sync(FULL, s,  off);
        ss += __shfl_xor_sync(FULL, ss, off);
    }
    __shared__ float rs[8], rss[8];
    int wid = tid >> 5, lane = tid & 31;
    if (!lane) { rs[wid] = s; rss[wid] = ss; }
    __syncthreads();
    if (tid == 0) {
        float a = 0.0f, c = 0.0f;
        #pragma unroll
        for (int w = 0; w < 8; w++) { a += rs[w]; c += rss[w]; }
        rs[0] = a; rss[0] = c;
    }
    __syncthreads();
    float mu   = rs[0] * (1.0f / D_);
    float var  = rss[0] * (1.0f / D_) - mu * mu;
    float rstd = rsqrtf(var + 1e-5f);
    #pragma unroll
    for (int i = 0; i < 3; i++) {
        int d = tid + i * 256;
        yr[d] = (v[i] - mu) * rstd * gamma[n * D_ + d] + beta[n * D_ + d];
    }
}

// ---------------------------------------------------------------------------
extern "C" void kernel_launch(void* const* d_in, const int* in_sizes, int n_in,
                              void* d_out, int out_size)
{
    const float* x     = (const float*)d_in[0];
    const float* hist  = (const float*)d_in[1];
    const int*   mask  = (const int*)  d_in[2];
    const float* Wq    = (const float*)d_in[3];
    const float* Wk    = (const float*)d_in[4];
    const float* Wv    = (const float*)d_in[5];
    const float* Wo    = (const float*)d_in[6];
    const float* gamma = (const float*)d_in[7];
    const float* beta  = (const float*)d_in[8];
    float* out = (float*)d_out;

    cudaFuncSetAttribute(proj_kv_mma, cudaFuncAttributeMaxDynamicSharedMemorySize, KV_SMEM);
    cudaFuncSetAttribute(proj_q_mma,  cudaFuncAttributeMaxDynamicSharedMemorySize, Q_SMEM);
    cudaFuncSetAttribute(attn_mma,    cudaFuncAttributeMaxDynamicSharedMemorySize, AT_SMEM);
    cudaFuncSetAttribute(outproj_mma, cudaFuncAttributeMaxDynamicSharedMemorySize, O_SMEM);

    transpose_weights<<<(N_DOM * I_ * D_ + 255) / 256, 256>>>(Wk, Wv, Wq, Wo, mask);

    proj_kv_mma<<<NBS / 128, 256, KV_SMEM>>>(hist);
    proj_q_mma <<<NBT / 128, 256, Q_SMEM>>>(x);

    float* bias_dev = nullptr;
    cudaGetSymbolAddress((void**)&bias_dev, g_bias);

    dim3 ag(T_ / 128, N_DOM * B_ * H_, NSPLIT);
    attn_mma<<<ag, 128, AT_SMEM>>>(bias_dev);

    attn_combine<<<(NBT * 16) / 256, 256>>>();

    dim3 og(NBT / 128, D_ / 128);
    outproj_mma<<<og, 256, O_SMEM>>>(x, out);

    ln_kernel<<<NBT, 256>>>(out, gamma, beta);
}

// round 13
// speedup vs baseline: 1.0992x; 1.0118x over previous
#include <cuda_runtime.h>
#include <cstdint>

#define N_DOM 6
#define B_    4
#define T_    1024
#define D_    768
#define P_    3
#define H_    2
#define DH    32
#define I_    64
#define S_    (P_*T_)          // 3072
#define NBT   (N_DOM*B_*T_)    // 24576
#define NBS   (N_DOM*B_*S_)    // 73728
#define SG_   (S_/8)           // 384 key-groups per (nb,h)
#define NSPLIT 3
#define NCHP  (S_/64/NSPLIT)   // 16 chunks per split

// Scratch (allocation-free rule: device globals)
__device__ float g_q[NBT*I_];
__device__ float g_k[NBS*I_];   // fragment-major: [nbh][sg][kd][lane]{x,y}
__device__ float g_v[NBS*I_];   // fragment-major: [nbh][sg][dt][lane]{x,y}
__device__ float g_o[NBT*I_];
__device__ float g_op[NSPLIT*NBT*I_];   // attention partials (unnormalized)
__device__ float g_lp[NSPLIT*NBT*2];    // partial row sums per (row, head)
__device__ float g_WkT[I_*D_];
__device__ float g_WvT[I_*D_];
__device__ float g_WqT[N_DOM*I_*D_];
__device__ float g_WoT[N_DOM*D_*I_];
__device__ float g_bias[B_*S_];  // (1-mask)*-10000*log2(e), pos8-permuted per 8-group

// ---------------------------------------------------------------------------
// helpers
// ---------------------------------------------------------------------------
__device__ __forceinline__ uint32_t smem_u32(const void* p) {
    uint32_t a;
    asm("{ .reg .u64 t; cvta.to.shared.u64 t, %1; cvt.u32.u64 %0, t; }" : "=r"(a) : "l"(p));
    return a;
}
__device__ __forceinline__ void cpa16(void* s, const void* g) {
    uint32_t sa = smem_u32(s);
    asm volatile("cp.async.cg.shared.global [%0], [%1], 16;" :: "r"(sa), "l"(g) : "memory");
}
#define CP_COMMIT() asm volatile("cp.async.commit_group;" ::: "memory")
#define CP_WAIT0()  asm volatile("cp.async.wait_group 0;" ::: "memory")
#define CP_WAIT1()  asm volatile("cp.async.wait_group 1;" ::: "memory")

__device__ __forceinline__ float to_tf32_rna(float x) {
    uint32_t u;
    asm("cvt.rna.tf32.f32 %0, %1;" : "=r"(u) : "f"(x));
    return __uint_as_float(u);
}
__device__ __forceinline__ uint32_t fbits(float x) { return __float_as_uint(x); }

__device__ __forceinline__ void mma8(float* c, const uint32_t* a, const uint32_t* b) {
    asm volatile(
        "mma.sync.aligned.m16n8k8.row.col.f32.tf32.tf32.f32 "
        "{%0,%1,%2,%3}, {%4,%5,%6,%7}, {%8,%9}, {%0,%1,%2,%3};"
        : "+f"(c[0]), "+f"(c[1]), "+f"(c[2]), "+f"(c[3])
        : "r"(a[0]), "r"(a[1]), "r"(a[2]), "r"(a[3]), "r"(b[0]), "r"(b[1]));
}

// permutation within 8-groups: logical r -> stored pos (pairs (r, r+4) adjacent)
__device__ __forceinline__ int pos8(int r) { return (r < 4) ? 2 * r : 2 * (r - 4) + 1; }

// ---------------------------------------------------------------------------
// Kernel 0: weight transpose (+tf32 round) and permuted bias table (log2 dom)
// ---------------------------------------------------------------------------
__global__ void __launch_bounds__(256) transpose_weights(
    const float* __restrict__ Wk, const float* __restrict__ Wv,
    const float* __restrict__ Wq, const float* __restrict__ Wo,
    const int* __restrict__ mask)
{
    int idx = blockIdx.x * 256 + threadIdx.x;
    if (idx < I_ * D_) {
        int i = idx / D_, d = idx % D_;
        g_WkT[idx] = to_tf32_rna(Wk[d * I_ + i]);
        g_WvT[idx] = to_tf32_rna(Wv[d * I_ + i]);
    }
    if (idx < N_DOM * I_ * D_) {
        int n = idx / (I_ * D_), r = idx % (I_ * D_);
        int i = r / D_, d = r % D_;
        g_WqT[idx] = to_tf32_rna(Wq[((size_t)n * D_ + d) * I_ + i]);
    }
    if (idx < N_DOM * D_ * I_) {
        int n = idx / (D_ * I_), r = idx % (D_ * I_);
        int d = r / I_, i = r % I_;
        g_WoT[idx] = to_tf32_rna(Wo[((size_t)n * I_ + i) * D_ + d]);
    }
    if (idx < B_ * S_) {
        int b = idx / S_, s = idx % S_;
        float v = (1.0f - (float)mask[b * T_ + (s % T_)]) * -10000.0f
                  * 1.4426950408889634f;
        g_bias[b * S_ + (s & ~7) + pos8(s & 7)] = v;   // key s stored at pos8(s)
    }
}

// ---------------------------------------------------------------------------
// Kernel 1: K+V projection. M=64 per block, 128 threads (4 warps), so
// smem=55.3KB -> 4 blocks/SM and grid 1152 ~= 2 clean waves.
// Inner loop / epilogue identical math to R12 (fragment-major K,V out).
// ---------------------------------------------------------------------------
#define KV_A_BUF   (64*36*4)               // 9216
#define KV_A_OFF   0
#define KV_BK_OFF  (2*KV_A_BUF)            // 18432
#define KV_B_BUF   (64*36*4)               // 9216
#define KV_BV_OFF  (KV_BK_OFF + 2*KV_B_BUF)// 36864
#define KV_SMEM    (KV_BV_OFF + 2*KV_B_BUF)// 55296

__global__ void __launch_bounds__(128, 4) proj_kv_mma(const float* __restrict__ hist)
{
    extern __shared__ char sm[];
    const int tid  = threadIdx.x;
    const int wid  = tid >> 5;
    const int lane = tid & 31;
    const int lr = lane >> 2, lc = lane & 3;
    const int m0 = (wid & 1) * 32;
    const int n0 = (wid >> 1) * 32;

    const int hr0 = blockIdx.x * 64;
    const float* Ab = hist + (size_t)hr0 * D_;

    auto stage = [&](int c, int buf) {
        int kk = c * 32;
        float* A  = (float*)(sm + KV_A_OFF  + buf * KV_A_BUF);
        float* Bk = (float*)(sm + KV_BK_OFF + buf * KV_B_BUF);
        float* Bv = (float*)(sm + KV_BV_OFF + buf * KV_B_BUF);
        #pragma unroll
        for (int q = 0; q < 4; q++) {        // A: 64 rows x 8 f4 = 512
            int e = tid + q * 128;
            int r = e >> 3, c4 = (e & 7) * 4;
            cpa16(&A[r * 36 + c4], Ab + (size_t)r * D_ + kk + c4);
        }
        #pragma unroll
        for (int q = 0; q < 4; q++) {        // Bk/Bv: 64 rows x 8 f4 each
            int e = tid + q * 128;
            int r = e >> 3, c4 = (e & 7) * 4;
            cpa16(&Bk[r * 36 + c4], g_WkT + (size_t)r * D_ + kk + c4);
            cpa16(&Bv[r * 36 + c4], g_WvT + (size_t)r * D_ + kk + c4);
        }
        CP_COMMIT();
    };

    float accK[2][4][4] = {};
    float accV[2][4][4] = {};

    stage(0, 0);
    #pragma unroll 1
    for (int c = 0; c < 24; c++) {
        int buf = c & 1;
        if (c + 1 < 24) { stage(c + 1, buf ^ 1); CP_WAIT1(); }
        else            { CP_WAIT0(); }
        __syncthreads();

        const float* A  = (const float*)(sm + KV_A_OFF + buf * KV_A_BUF);
        const float* Bk = (const float*)(sm + KV_BK_OFF + buf * KV_B_BUF);
        const float* Bv = (const float*)(sm + KV_BV_OFF + buf * KV_B_BUF);

        #pragma unroll
        for (int ks = 0; ks < 4; ks++) {
            int k0 = ks * 8;
            uint32_t af[2][4];
            #pragma unroll
            for (int mt = 0; mt < 2; mt++) {
                int r = m0 + mt * 16 + lr;
                af[mt][0] = fbits(A[r * 36 + k0 + lc]);
                af[mt][1] = fbits(A[(r + 8) * 36 + k0 + lc]);
                af[mt][2] = fbits(A[r * 36 + k0 + lc + 4]);
                af[mt][3] = fbits(A[(r + 8) * 36 + k0 + lc + 4]);
            }
            uint32_t bk[4][2], bv[4][2];
            #pragma unroll
            for (int nt = 0; nt < 4; nt++) {
                int nn = n0 + nt * 8 + lr;
                bk[nt][0] = fbits(Bk[nn * 36 + k0 + lc]);
                bk[nt][1] = fbits(Bk[nn * 36 + k0 + lc + 4]);
                bv[nt][0] = fbits(Bv[nn * 36 + k0 + lc]);
                bv[nt][1] = fbits(Bv[nn * 36 + k0 + lc + 4]);
            }
            #pragma unroll
            for (int mt = 0; mt < 2; mt++)
                #pragma unroll
                for (int nt = 0; nt < 4; nt++) {
                    mma8(accK[mt][nt], af[mt], bk[nt]);
                    mma8(accV[mt][nt], af[mt], bv[nt]);
                }
        }
        __syncthreads();
    }

    int p  = hr0 / (N_DOM * B_ * T_);
    int r1 = hr0 % (N_DOM * B_ * T_);
    int n  = r1 / (B_ * T_);
    int r2 = r1 % (B_ * T_);
    int b  = r2 / T_, t0 = r2 % T_;
    const int nb   = n * B_ + b;
    const int sbb  = p * T_ + t0;
    const int head = n0 >> 5;
    const int nbh  = nb * 2 + head;

    const int lrK   = pos8(lr);
    const int lcK0  = (2 * lc) & 3;
    const int lcK1  = (2 * lc + 1) & 3;
    const int compK = (lc >= 2);
    const int lcV   = lr & 3;
    const int compV = (lr >= 4);

    #pragma unroll
    for (int mt = 0; mt < 2; mt++) {
        int sg = (sbb + m0 + mt * 16) >> 3;
        #pragma unroll
        for (int nt = 0; nt < 4; nt++) {
            size_t base  = ((size_t)(nbh * SG_ + sg) * 4 + nt) * 64;
            size_t base2 = base + 4 * 64;
            g_k[base  + (lrK * 4 + lcK0) * 2 + compK] = accK[mt][nt][0];
            g_k[base  + (lrK * 4 + lcK1) * 2 + compK] = accK[mt][nt][1];
            g_k[base2 + (lrK * 4 + lcK0) * 2 + compK] = accK[mt][nt][2];
            g_k[base2 + (lrK * 4 + lcK1) * 2 + compK] = accK[mt][nt][3];
            g_v[base  + ((2 * lc)     * 4 + lcV) * 2 + compV] = accV[mt][nt][0];
            g_v[base  + ((2 * lc + 1) * 4 + lcV) * 2 + compV] = accV[mt][nt][1];
            g_v[base2 + ((2 * lc)     * 4 + lcV) * 2 + compV] = accV[mt][nt][2];
            g_v[base2 + ((2 * lc + 1) * 4 + lcV) * 2 + compV] = accV[mt][nt][3];
        }
    }
}

// ---------------------------------------------------------------------------
// Kernel 2: Q projection. M=64 per block, 128 threads (4 warps) -> grid 384.
// ---------------------------------------------------------------------------
#define Q_A_BUF   (64*36*4)                // 9216
#define Q_A_OFF   0
#define Q_B_OFF   (2*Q_A_BUF)              // 18432
#define Q_B_BUF   (64*36*4)
#define Q_SMEM    (Q_B_OFF + 2*Q_B_BUF)    // 36864

__global__ void __launch_bounds__(128, 4) proj_q_mma(const float* __restrict__ x)
{
    extern __shared__ char sm[];
    const int tid  = threadIdx.x;
    const int wid  = tid >> 5;
    const int lane = tid & 31;
    const int lr = lane >> 2, lc = lane & 3;
    const int m0 = (wid & 1) * 32;
    const int n0 = (wid >> 1) * 32;

    const int row0 = blockIdx.x * 64;
    const int n = row0 / (B_ * T_);
    const float* Ab = x + (size_t)row0 * D_;
    const float* Wb = g_WqT + (size_t)n * I_ * D_;

    auto stage = [&](int c, int buf) {
        int kk = c * 32;
        float* A  = (float*)(sm + Q_A_OFF + buf * Q_A_BUF);
        float* Bq = (float*)(sm + Q_B_OFF + buf * Q_B_BUF);
        #pragma unroll
        for (int q = 0; q < 4; q++) {
            int e = tid + q * 128;
            int r = e >> 3, c4 = (e & 7) * 4;
            cpa16(&A[r * 36 + c4], Ab + (size_t)r * D_ + kk + c4);
        }
        #pragma unroll
        for (int q = 0; q < 4; q++) {
            int e = tid + q * 128;
            int r = e >> 3, c4 = (e & 7) * 4;
            cpa16(&Bq[r * 36 + c4], Wb + (size_t)r * D_ + kk + c4);
        }
        CP_COMMIT();
    };

    float acc[2][4][4] = {};

    stage(0, 0);
    #pragma unroll 1
    for (int c = 0; c < 24; c++) {
        int buf = c & 1;
        if (c + 1 < 24) { stage(c + 1, buf ^ 1); CP_WAIT1(); }
        else            { CP_WAIT0(); }
        __syncthreads();

        const float* A  = (const float*)(sm + Q_A_OFF + buf * Q_A_BUF);
        const float* Bq = (const float*)(sm + Q_B_OFF + buf * Q_B_BUF);

        #pragma unroll
        for (int ks = 0; ks < 4; ks++) {
            int k0 = ks * 8;
            uint32_t af[2][4];
            #pragma unroll
            for (int mt = 0; mt < 2; mt++) {
                int r = m0 + mt * 16 + lr;
                af[mt][0] = fbits(A[r * 36 + k0 + lc]);
                af[mt][1] = fbits(A[(r + 8) * 36 + k0 + lc]);
                af[mt][2] = fbits(A[r * 36 + k0 + lc + 4]);
                af[mt][3] = fbits(A[(r + 8) * 36 + k0 + lc + 4]);
            }
            uint32_t bq[4][2];
            #pragma unroll
            for (int nt = 0; nt < 4; nt++) {
                int nn = n0 + nt * 8 + lr;
                bq[nt][0] = fbits(Bq[nn * 36 + k0 + lc]);
                bq[nt][1] = fbits(Bq[nn * 36 + k0 + lc + 4]);
            }
            #pragma unroll
            for (int mt = 0; mt < 2; mt++)
                #pragma unroll
                for (int nt = 0; nt < 4; nt++)
                    mma8(acc[mt][nt], af[mt], bq[nt]);
        }
        __syncthreads();
    }

    #pragma unroll
    for (int mt = 0; mt < 2; mt++)
        #pragma unroll
        for (int nt = 0; nt < 4; nt++) {
            int row = row0 + m0 + mt * 16 + lr;
            int col = n0 + nt * 8 + lc * 2;
            *(float2*)&g_q[(size_t)row * I_ + col]       = make_float2(acc[mt][nt][0], acc[mt][nt][1]);
            *(float2*)&g_q[(size_t)(row + 8) * I_ + col] = make_float2(acc[mt][nt][2], acc[mt][nt][3]);
        }
}

// ---------------------------------------------------------------------------
// Kernel 3: flash attention, 3-way split over keys (UNCHANGED R12).
// ---------------------------------------------------------------------------
#define AT_K_BUF  8192
#define AT_V_BUF  8192
#define AT_V_OFF  (3*AT_K_BUF)             // 24576
#define AT_B_OFF  (AT_V_OFF + 3*AT_V_BUF)  // 49152
#define AT_SMEM   (AT_B_OFF + 3*256)       // 49920

__global__ void __launch_bounds__(128, 4) attn_mma(const float* __restrict__ gbias)
{
    extern __shared__ char sm[];
    const int tid  = threadIdx.x;
    const int wid  = tid >> 5;
    const int lane = tid & 31;
    const int lr = lane >> 2, lc = lane & 3;

    const int nbh = blockIdx.y;
    const int h   = nbh % H_;
    const int nb  = nbh / H_;
    const int b   = nb % B_;
    const int q0  = blockIdx.x * 128;
    const int sp  = blockIdx.z;
    const int cb  = sp * NCHP;

    const float* qg = g_q + ((size_t)nb * T_ + q0) * I_ + h * DH;
    const float* kg = g_k + (size_t)(nb * 2 + h) * SG_ * 256;
    const float* vg = g_v + (size_t)(nb * 2 + h) * SG_ * 256;
    const float* bg = gbias + b * S_;

    auto stage = [&](int c, int buf) {
        float* K  = (float*)(sm + buf * AT_K_BUF);
        float* V  = (float*)(sm + AT_V_OFF + buf * AT_V_BUF);
        float* Bb = (float*)(sm + AT_B_OFF + buf * 256);
        const float* kc = kg + (size_t)(cb + c) * 2048;
        const float* vc = vg + (size_t)(cb + c) * 2048;
        #pragma unroll
        for (int q = 0; q < 4; q++) {
            int e = (tid + q * 128) * 4;
            cpa16(&K[e], kc + e);
            cpa16(&V[e], vc + e);
        }
        if (tid < 16) cpa16(&Bb[tid * 4], bg + (cb + c) * 64 + tid * 4);
        CP_COMMIT();
    };

    stage(0, 0);
    stage(1, 1);

    const float scale = 0.17677669529663687f * 1.4426950408889634f;
    uint32_t aQ[2][4][4];
    #pragma unroll
    for (int mt = 0; mt < 2; mt++) {
        const float* qr  = qg + (size_t)(wid * 32 + mt * 16 + lr) * I_;
        const float* qr8 = qr + 8 * I_;
        #pragma unroll
        for (int kd = 0; kd < 4; kd++) {
            aQ[mt][kd][0] = fbits(qr[kd * 8 + lc] * scale);
            aQ[mt][kd][1] = fbits(qr8[kd * 8 + lc] * scale);
            aQ[mt][kd][2] = fbits(qr[kd * 8 + lc + 4] * scale);
            aQ[mt][kd][3] = fbits(qr8[kd * 8 + lc + 4] * scale);
        }
    }

    float oacc[2][4][4] = {};
    float lsum[4] = {};

    #pragma unroll 1
    for (int c = 0; c < NCHP; c++) {
        if (c + 1 < NCHP) CP_WAIT1(); else CP_WAIT0();
        __syncthreads();
        if (c + 2 < NCHP) stage(c + 2, (c + 2) % 3);

        int buf = c % 3;
        const float2* kf = (const float2*)(sm + buf * AT_K_BUF);
        const float2* vf = (const float2*)(sm + AT_V_OFF + buf * AT_V_BUF);
        const float*  Bb = (const float*)(sm + AT_B_OFF + buf * 256);

        #pragma unroll
        for (int half = 0; half < 2; half++) {
            const int stb = half * 4;

            float sc[2][4][4] = {};
            #pragma unroll
            for (int kd = 0; kd < 4; kd++) {
                #pragma unroll
                for (int st = 0; st < 4; st++) {
                    float2 kv = kf[((stb + st) * 4 + kd) * 32 + lane];
                    uint32_t bb[2] = { fbits(kv.x), fbits(kv.y) };
                    mma8(sc[0][st], aQ[0][kd], bb);
                    mma8(sc[1][st], aQ[1][kd], bb);
                }
            }

            #pragma unroll
            for (int st = 0; st < 4; st++) {
                float2 bv = *(const float2*)&Bb[(stb + st) * 8 + 2 * lc];
                #pragma unroll
                for (int mt = 0; mt < 2; mt++) {
                    sc[mt][st][0] = exp2f(sc[mt][st][0] + bv.x); lsum[mt * 2]     += sc[mt][st][0];
                    sc[mt][st][1] = exp2f(sc[mt][st][1] + bv.y); lsum[mt * 2]     += sc[mt][st][1];
                    sc[mt][st][2] = exp2f(sc[mt][st][2] + bv.x); lsum[mt * 2 + 1] += sc[mt][st][2];
                    sc[mt][st][3] = exp2f(sc[mt][st][3] + bv.y); lsum[mt * 2 + 1] += sc[mt][st][3];
                }
            }

            #pragma unroll
            for (int st = 0; st < 4; st++) {
                uint32_t aP0[4] = { fbits(sc[0][st][0]), fbits(sc[0][st][2]),
                                    fbits(sc[0][st][1]), fbits(sc[0][st][3]) };
                uint32_t aP1[4] = { fbits(sc[1][st][0]), fbits(sc[1][st][2]),
                                    fbits(sc[1][st][1]), fbits(sc[1][st][3]) };
                #pragma unroll
                for (int dt = 0; dt < 4; dt++) {
                    float2 vv = vf[((stb + st) * 4 + dt) * 32 + lane];
                    uint32_t bb[2] = { fbits(vv.x), fbits(vv.y) };
                    mma8(oacc[0][dt], aP0, bb);
                    mma8(oacc[1][dt], aP1, bb);
                }
            }
        }
    }

    const unsigned FULL = 0xffffffffu;
    #pragma unroll
    for (int i = 0; i < 4; i++) {
        lsum[i] += __shfl_xor_sync(FULL, lsum[i], 1);
        lsum[i] += __shfl_xor_sync(FULL, lsum[i], 2);
    }

    float* op = g_op + (size_t)sp * NBT * I_;
    #pragma unroll
    for (int mt = 0; mt < 2; mt++) {
        int row = nb * T_ + q0 + wid * 32 + mt * 16 + lr;
        #pragma unroll
        for (int dt = 0; dt < 4; dt++) {
            int col = h * DH + dt * 8 + 2 * lc;
            *(float2*)&op[(size_t)row * I_ + col] =
                make_float2(oacc[mt][dt][0], oacc[mt][dt][1]);
            *(float2*)&op[(size_t)(row + 8) * I_ + col] =
                make_float2(oacc[mt][dt][2], oacc[mt][dt][3]);
        }
        if (lc == 0) {
            g_lp[((size_t)sp * NBT + row) * 2 + h]     = lsum[mt * 2];
            g_lp[((size_t)sp * NBT + row + 8) * 2 + h] = lsum[mt * 2 + 1];
        }
    }
}

// ---------------------------------------------------------------------------
// Kernel 3b: combine split partials (UNCHANGED R12)
// ---------------------------------------------------------------------------
__global__ void __launch_bounds__(256) attn_combine()
{
    int idx = blockIdx.x * 256 + threadIdx.x;
    int row = idx >> 4;
    int c4  = idx & 15;
    int h   = c4 >> 3;

    size_t eo = (size_t)row * I_ + c4 * 4;
    float4 a0 = *(const float4*)&g_op[eo];
    float4 a1 = *(const float4*)&g_op[(size_t)NBT * I_ + eo];
    float4 a2 = *(const float4*)&g_op[(size_t)2 * NBT * I_ + eo];
    float l = g_lp[(size_t)row * 2 + h]
            + g_lp[((size_t)NBT + row) * 2 + h]
            + g_lp[((size_t)2 * NBT + row) * 2 + h];
    float inv = 1.0f / l;
    *(float4*)&g_o[eo] = make_float4((a0.x + a1.x + a2.x) * inv,
                                     (a0.y + a1.y + a2.y) * inv,
                                     (a0.z + a1.z + a2.z) * inv,
                                     (a0.w + a1.w + a2.w) * inv);
}

// ---------------------------------------------------------------------------
// Kernel 4: out projection + residual (UNCHANGED R12)
// ---------------------------------------------------------------------------
#define O_A_OFF  0
#define O_A_SZ   (128*68*4)
#define O_B_OFF  O_A_SZ
#define O_SMEM   (2*O_A_SZ)

__global__ void __launch_bounds__(256) outproj_mma(
    const float* __restrict__ x, float* __restrict__ out)
{
    extern __shared__ char sm[];
    const int tid  = threadIdx.x;
    const int wid  = tid >> 5;
    const int lane = tid & 31;
    const int lr = lane >> 2, lc = lane & 3;
    const int m0 = (wid & 3) * 32;
    const int n0 = (wid >> 2) * 64;

    const int row0 = blockIdx.x * 128;
    const int col0 = blockIdx.y * 128;
    const int n = row0 / (B_ * T_);

    float* A = (float*)(sm + O_A_OFF);
    float* B = (float*)(sm + O_B_OFF);

    #pragma unroll
    for (int q = 0; q < 8; q++) {
        int e = tid + q * 256;
        int r = e >> 4, c4 = (e & 15) * 4;
        cpa16(&A[r * 68 + c4], g_o + (size_t)(row0 + r) * I_ + c4);
    }
    #pragma unroll
    for (int q = 0; q < 8; q++) {
        int e = tid + q * 256;
        int r = e >> 4, c4 = (e & 15) * 4;
        cpa16(&B[r * 68 + c4], g_WoT + ((size_t)n * D_ + col0 + r) * I_ + c4);
    }
    CP_COMMIT();
    CP_WAIT0();
    __syncthreads();

    float acc[2][8][4] = {};
    #pragma unroll
    for (int ks = 0; ks < 8; ks++) {
        int k0 = ks * 8;
        uint32_t af[2][4];
        #pragma unroll
        for (int mt = 0; mt < 2; mt++) {
            int r = m0 + mt * 16 + lr;
            af[mt][0] = fbits(A[r * 68 + k0 + lc]);
            af[mt][1] = fbits(A[(r + 8) * 68 + k0 + lc]);
            af[mt][2] = fbits(A[r * 68 + k0 + lc + 4]);
            af[mt][3] = fbits(A[(r + 8) * 68 + k0 + lc + 4]);
        }
        #pragma unroll
        for (int nt = 0; nt < 8; nt++) {
            int nn = n0 + nt * 8 + lr;
            uint32_t bf[2];
            bf[0] = fbits(B[nn * 68 + k0 + lc]);
            bf[1] = fbits(B[nn * 68 + k0 + lc + 4]);
            mma8(acc[0][nt], af[0], bf);
            mma8(acc[1][nt], af[1], bf);
        }
    }

    #pragma unroll
    for (int mt = 0; mt < 2; mt++)
        #pragma unroll
        for (int nt = 0; nt < 8; nt++) {
            int row = row0 + m0 + mt * 16 + lr;
            int col = col0 + n0 + nt * 8 + lc * 2;
            float2 x0 = *(const float2*)&x[(size_t)row * D_ + col];
            float2 x1 = *(const float2*)&x[(size_t)(row + 8) * D_ + col];
            *(float2*)&out[(size_t)row * D_ + col] =
                make_float2(acc[mt][nt][0] + x0.x, acc[mt][nt][1] + x0.y);
            *(float2*)&out[(size_t)(row + 8) * D_ + col] =
                make_float2(acc[mt][nt][2] + x1.x, acc[mt][nt][3] + x1.y);
        }
}

// ---------------------------------------------------------------------------
// Kernel 5: LayerNorm in place on d_out. (UNCHANGED)
// ---------------------------------------------------------------------------
__global__ void __launch_bounds__(256) ln_kernel(
    float* __restrict__ y,
    const float* __restrict__ gamma,
    const float* __restrict__ beta)
{
    const int row = blockIdx.x;
    const int n   = row / (B_ * T_);
    float* yr = y + (size_t)row * D_;
    const int tid = threadIdx.x;

    float v[3];
    float s = 0.0f, ss = 0.0f;
    #pragma unroll
    for (int i = 0; i < 3; i++) {
        v[i] = yr[tid + i * 256];
        s  += v[i];
        ss += v[i] * v[i];
    }
    const unsigned FULL = 0xffffffffu;
    #pragma unroll
    for (int off = 16; off; off >>= 1) {
        s  += __shfl_xor_sync(FULL, s,  off);
        ss += __shfl_xor_sync(FULL, ss, off);
    }
    __shared__ float rs[8], rss[8];
    int wid = tid >> 5, lane = tid & 31;
    if (!lane) { rs[wid] = s; rss[wid] = ss; }
    __syncthreads();
    if (tid == 0) {
        float a = 0.0f, c = 0.0f;
        #pragma unroll
        for (int w = 0; w < 8; w++) { a += rs[w]; c += rss[w]; }
        rs[0] = a; rss[0] = c;
    }
    __syncthreads();
    float mu   = rs[0] * (1.0f / D_);
    float var  = rss[0] * (1.0f / D_) - mu * mu;
    float rstd = rsqrtf(var + 1e-5f);
    #pragma unroll
    for (int i = 0; i < 3; i++) {
        int d = tid + i * 256;
        yr[d] = (v[i] - mu) * rstd * gamma[n * D_ + d] + beta[n * D_ + d];
    }
}

// ---------------------------------------------------------------------------
extern "C" void kernel_launch(void* const* d_in, const int* in_sizes, int n_in,
                              void* d_out, int out_size)
{
    const float* x     = (const float*)d_in[0];
    const float* hist  = (const float*)d_in[1];
    const int*   mask  = (const int*)  d_in[2];
    const float* Wq    = (const float*)d_in[3];
    const float* Wk    = (const float*)d_in[4];
    const float* Wv    = (const float*)d_in[5];
    const float* Wo    = (const float*)d_in[6];
    const float* gamma = (const float*)d_in[7];
    const float* beta  = (const float*)d_in[8];
    float* out = (float*)d_out;

    cudaFuncSetAttribute(proj_kv_mma, cudaFuncAttributeMaxDynamicSharedMemorySize, KV_SMEM);
    cudaFuncSetAttribute(proj_q_mma,  cudaFuncAttributeMaxDynamicSharedMemorySize, Q_SMEM);
    cudaFuncSetAttribute(attn_mma,    cudaFuncAttributeMaxDynamicSharedMemorySize, AT_SMEM);
    cudaFuncSetAttribute(outproj_mma, cudaFuncAttributeMaxDynamicSharedMemorySize, O_SMEM);

    transpose_weights<<<(N_DOM * I_ * D_ + 255) / 256, 256>>>(Wk, Wv, Wq, Wo, mask);

    proj_kv_mma<<<NBS / 64, 128, KV_SMEM>>>(hist);
    proj_q_mma <<<NBT / 64, 128, Q_SMEM>>>(x);

    float* bias_dev = nullptr;
    cudaGetSymbolAddress((void**)&bias_dev, g_bias);

    dim3 ag(T_ / 128, N_DOM * B_ * H_, NSPLIT);
    attn_mma<<<ag, 128, AT_SMEM>>>(bias_dev);

    attn_combine<<<(NBT * 16) / 256, 256>>>();

    dim3 og(NBT / 128, D_ / 128);
    outproj_mma<<<og, 256, O_SMEM>>>(x, out);

    ln_kernel<<<NBT, 256>>>(out, gamma, beta);
}